// round 4
// baseline (speedup 1.0000x reference)
#include <cuda_runtime.h>
#include <cstddef>

#define NB 4
#define NS 2048
#define NDIM 768
#define NH 12
#define HD 64
#define NHID 3072
#define NM (NB*NS)          // 8192 rows
#define QKVLD 2304
#define SCALE 0.125f        // 64^-0.5

// ---------------- scratch (device globals: allocation-guard safe) ------------
__device__ float g_h[(size_t)NM * NDIM];      // LN output (reused for both LNs)
__device__ float g_buf[(size_t)NM * NHID];    // qkv (8192x2304) then mlp hidden (8192x3072)
__device__ float g_attn[(size_t)NM * NDIM];   // attention output
__device__ float g_x2[(size_t)NM * NDIM];     // residual stream after attn block

// ---------------- LayerNorm: one block (256 thr) per token -------------------
__global__ __launch_bounds__(256)
void ln_kernel(const float* __restrict__ x, const float* __restrict__ g,
               const float* __restrict__ be, float* __restrict__ out) {
    int row = blockIdx.x;
    const float* xr = x + (size_t)row * NDIM;
    int tid = threadIdx.x;
    float v0 = xr[tid], v1 = xr[tid + 256], v2 = xr[tid + 512];
    float s  = v0 + v1 + v2;
    float s2 = v0 * v0 + v1 * v1 + v2 * v2;
#pragma unroll
    for (int o = 16; o; o >>= 1) {
        s  += __shfl_xor_sync(0xffffffffu, s,  o);
        s2 += __shfl_xor_sync(0xffffffffu, s2, o);
    }
    __shared__ float rs[8], rs2[8];
    int w = tid >> 5, ln = tid & 31;
    if (ln == 0) { rs[w] = s; rs2[w] = s2; }
    __syncthreads();
    if (w == 0) {
        s  = (ln < 8) ? rs[ln]  : 0.f;
        s2 = (ln < 8) ? rs2[ln] : 0.f;
#pragma unroll
        for (int o = 4; o; o >>= 1) {
            s  += __shfl_xor_sync(0xffffffffu, s,  o);
            s2 += __shfl_xor_sync(0xffffffffu, s2, o);
        }
        if (ln == 0) { rs[0] = s; rs2[0] = s2; }
    }
    __syncthreads();
    float mu  = rs[0] * (1.0f / NDIM);
    float var = rs2[0] * (1.0f / NDIM) - mu * mu;
    float inv = rsqrtf(var + 1e-6f);
    float* orow = out + (size_t)row * NDIM;
    orow[tid      ] = (v0 - mu) * inv * g[tid      ] + be[tid      ];
    orow[tid + 256] = (v1 - mu) * inv * g[tid + 256] + be[tid + 256];
    orow[tid + 512] = (v2 - mu) * inv * g[tid + 512] + be[tid + 512];
}

// ---------------- fp32 tiled GEMM: C[M,N] = A[M,K] @ B[K,N] + epilogue -------
// EPI: 0 = +bias ; 1 = +bias +res ; 2 = +bias then exact GELU
template <int EPI>
__global__ __launch_bounds__(256)
void gemm_kernel(const float* __restrict__ A, const float* __restrict__ Bm,
                 const float* __restrict__ bias, const float* __restrict__ res,
                 float* __restrict__ C, int M, int N, int K) {
    __shared__ float As[8][128];
    __shared__ float Bs[8][128];
    const int tid = threadIdx.x;
    const int tx = tid & 15, ty = tid >> 4;
    const size_t mbase = (size_t)blockIdx.y * 128;
    const int nbase = blockIdx.x * 128;

    const int arow = tid >> 1, acol = (tid & 1) * 4;
    const int brow = tid >> 5, bcol = (tid & 31) * 4;
    const float* Ap = A + (mbase + arow) * K + acol;
    const float* Bp = Bm + (size_t)brow * N + nbase + bcol;

    float acc[8][8];
#pragma unroll
    for (int i = 0; i < 8; i++)
#pragma unroll
        for (int j = 0; j < 8; j++) acc[i][j] = 0.f;

    for (int k0 = 0; k0 < K; k0 += 8) {
        float4 av = *(const float4*)(Ap + k0);
        float4 bv = *(const float4*)(Bp + (size_t)k0 * N);
        __syncthreads();
        As[acol + 0][arow] = av.x;
        As[acol + 1][arow] = av.y;
        As[acol + 2][arow] = av.z;
        As[acol + 3][arow] = av.w;
        *(float4*)&Bs[brow][bcol] = bv;
        __syncthreads();
#pragma unroll
        for (int kk = 0; kk < 8; kk++) {
            float a[8], b[8];
            *(float4*)&a[0] = *(const float4*)&As[kk][ty * 8];
            *(float4*)&a[4] = *(const float4*)&As[kk][ty * 8 + 4];
            *(float4*)&b[0] = *(const float4*)&Bs[kk][tx * 8];
            *(float4*)&b[4] = *(const float4*)&Bs[kk][tx * 8 + 4];
#pragma unroll
            for (int i = 0; i < 8; i++)
#pragma unroll
                for (int j = 0; j < 8; j++)
                    acc[i][j] = fmaf(a[i], b[j], acc[i][j]);
        }
    }

    const size_t row0 = mbase + (size_t)ty * 8;
    const int col0 = nbase + tx * 8;
#pragma unroll
    for (int i = 0; i < 8; i++) {
        size_t r = row0 + i;
#pragma unroll
        for (int j = 0; j < 8; j++) {
            int c = col0 + j;
            float v = acc[i][j] + bias[c];
            if (EPI == 1) v += res[r * N + c];
            if (EPI == 2) v = 0.5f * v * (1.0f + erff(v * 0.70710678118654752f));
            C[r * N + c] = v;
        }
    }
}

// ---------------- Attention: online-softmax, 128 q-rows per block ------------
__global__ __launch_bounds__(128)
void attn_kernel(const float* __restrict__ qkv, const int* __restrict__ mask,
                 float* __restrict__ out) {
    constexpr int TK = 16;
    const int q0 = blockIdx.x * 128;
    const int h  = blockIdx.y;
    const int b  = blockIdx.z;
    const int tid = threadIdx.x;

    __shared__ __align__(16) float q_s[128][68];   // pad 68 -> conflict-free float4
    __shared__ __align__(16) float k_s[TK][64];
    __shared__ __align__(16) float v_s[TK][64];

    // stage Q tile
    const float* qbase = qkv + (size_t)(b * NS + q0) * QKVLD + h * HD;
#pragma unroll
    for (int it = 0; it < 16; it++) {
        int i = tid + it * 128;
        int r = i >> 4, c4 = (i & 15) * 4;
        *(float4*)&q_s[r][c4] = *(const float4*)(qbase + (size_t)r * QKVLD + c4);
    }

    const float* kbase = qkv + (size_t)b * NS * QKVLD + NDIM + h * HD;
    const float* vbase = kbase + NDIM;
    const int* mrow = mask + (size_t)b * NS * NS + (size_t)(q0 + tid) * NS;

    float mx = -1e30f, l = 0.f;
    float acc[HD];
#pragma unroll
    for (int d = 0; d < HD; d++) acc[d] = 0.f;

    for (int k0 = 0; k0 < NS; k0 += TK) {
        __syncthreads();
        {   // stage K/V tiles: 256 float4 each, 128 threads -> 2 apiece
            int i0 = tid, i1 = tid + 128;
            int r0 = i0 >> 4, c0 = (i0 & 15) * 4;
            int r1 = i1 >> 4, c1 = (i1 & 15) * 4;
            *(float4*)&k_s[r0][c0] = *(const float4*)(kbase + (size_t)(k0 + r0) * QKVLD + c0);
            *(float4*)&k_s[r1][c1] = *(const float4*)(kbase + (size_t)(k0 + r1) * QKVLD + c1);
            *(float4*)&v_s[r0][c0] = *(const float4*)(vbase + (size_t)(k0 + r0) * QKVLD + c0);
            *(float4*)&v_s[r1][c1] = *(const float4*)(vbase + (size_t)(k0 + r1) * QKVLD + c1);
        }
        __syncthreads();

        float s[TK];
#pragma unroll
        for (int kk = 0; kk < TK; kk++) s[kk] = 0.f;
#pragma unroll
        for (int d4 = 0; d4 < 16; d4++) {
            float4 qv = *(const float4*)&q_s[tid][d4 * 4];
#pragma unroll
            for (int kk = 0; kk < TK; kk++) {
                float4 kv = *(const float4*)&k_s[kk][d4 * 4];
                s[kk] += qv.x * kv.x + qv.y * kv.y + qv.z * kv.z + qv.w * kv.w;
            }
        }

        // mask + scale (exactly match reference: masked -> -10000 after scaling)
#pragma unroll
        for (int i4 = 0; i4 < TK / 4; i4++) {
            int4 mv = *(const int4*)(mrow + k0 + i4 * 4);
            s[i4 * 4 + 0] = (mv.x == 0) ? -10000.f : s[i4 * 4 + 0] * SCALE;
            s[i4 * 4 + 1] = (mv.y == 0) ? -10000.f : s[i4 * 4 + 1] * SCALE;
            s[i4 * 4 + 2] = (mv.z == 0) ? -10000.f : s[i4 * 4 + 2] * SCALE;
            s[i4 * 4 + 3] = (mv.w == 0) ? -10000.f : s[i4 * 4 + 3] * SCALE;
        }

        float tmax = -1e30f;
#pragma unroll
        for (int kk = 0; kk < TK; kk++) tmax = fmaxf(tmax, s[kk]);
        float nm = fmaxf(mx, tmax);
        float corr = __expf(mx - nm);
        l *= corr;
#pragma unroll
        for (int d = 0; d < HD; d++) acc[d] *= corr;
#pragma unroll
        for (int kk = 0; kk < TK; kk++) {
            float p = __expf(s[kk] - nm);
            l += p;
            s[kk] = p;
        }
#pragma unroll
        for (int kk = 0; kk < TK; kk++) {
            float p = s[kk];
#pragma unroll
            for (int d4 = 0; d4 < 16; d4++) {
                float4 vv = *(const float4*)&v_s[kk][d4 * 4];
                acc[d4 * 4 + 0] = fmaf(p, vv.x, acc[d4 * 4 + 0]);
                acc[d4 * 4 + 1] = fmaf(p, vv.y, acc[d4 * 4 + 1]);
                acc[d4 * 4 + 2] = fmaf(p, vv.z, acc[d4 * 4 + 2]);
                acc[d4 * 4 + 3] = fmaf(p, vv.w, acc[d4 * 4 + 3]);
            }
        }
        mx = nm;
    }

    float invl = 1.0f / l;
    float* orow = out + (size_t)(b * NS + q0 + tid) * NDIM + h * HD;
#pragma unroll
    for (int d4 = 0; d4 < 16; d4++) {
        float4 o;
        o.x = acc[d4 * 4 + 0] * invl;
        o.y = acc[d4 * 4 + 1] * invl;
        o.z = acc[d4 * 4 + 2] * invl;
        o.w = acc[d4 * 4 + 3] * invl;
        *(float4*)(orow + d4 * 4) = o;
    }
}

// ---------------- launch ------------------------------------------------------
extern "C" void kernel_launch(void* const* d_in, const int* in_sizes, int n_in,
                              void* d_out, int out_size) {
    const float* x      = (const float*)d_in[0];
    const int*   mask   = (const int*)  d_in[1];
    const float* w_qkv  = (const float*)d_in[2];
    const float* b_qkv  = (const float*)d_in[3];
    const float* w_proj = (const float*)d_in[4];
    const float* b_proj = (const float*)d_in[5];
    const float* g1     = (const float*)d_in[6];
    const float* be1    = (const float*)d_in[7];
    const float* g2     = (const float*)d_in[8];
    const float* be2    = (const float*)d_in[9];
    const float* w1     = (const float*)d_in[10];
    const float* b1     = (const float*)d_in[11];
    const float* w2     = (const float*)d_in[12];
    const float* b2     = (const float*)d_in[13];
    float* out = (float*)d_out;

    float *h_p, *buf_p, *attn_p, *x2_p;
    cudaGetSymbolAddress((void**)&h_p,    g_h);
    cudaGetSymbolAddress((void**)&buf_p,  g_buf);
    cudaGetSymbolAddress((void**)&attn_p, g_attn);
    cudaGetSymbolAddress((void**)&x2_p,   g_x2);

    // 1) h = LN1(x)
    ln_kernel<<<NM, 256>>>(x, g1, be1, h_p);
    // 2) qkv = h @ w_qkv + b_qkv
    gemm_kernel<0><<<dim3(QKVLD / 128, NM / 128), 256>>>(h_p, w_qkv, b_qkv, nullptr, buf_p, NM, QKVLD, NDIM);
    // 3) attention
    attn_kernel<<<dim3(NS / 128, NH, NB), 128>>>(buf_p, mask, attn_p);
    // 4) x2 = x + attn @ w_proj + b_proj
    gemm_kernel<1><<<dim3(NDIM / 128, NM / 128), 256>>>(attn_p, w_proj, b_proj, x, x2_p, NM, NDIM, NDIM);
    // 5) h = LN2(x2)
    ln_kernel<<<NM, 256>>>(x2_p, g2, be2, h_p);
    // 6) hid = gelu(h @ w1 + b1)
    gemm_kernel<2><<<dim3(NHID / 128, NM / 128), 256>>>(h_p, w1, b1, nullptr, buf_p, NM, NHID, NDIM);
    // 7) out = x2 + hid @ w2 + b2
    gemm_kernel<1><<<dim3(NDIM / 128, NM / 128), 256>>>(buf_p, w2, b2, x2_p, out, NM, NDIM, NHID);
}

// round 7
// speedup vs baseline: 1.5036x; 1.5036x over previous
#include <cuda_runtime.h>
#include <cuda_bf16.h>
#include <cstdint>
#include <cstddef>

#define NB 4
#define NS 2048
#define NDIM 768
#define NH 12
#define HD 64
#define NHID 3072
#define NM (NB*NS)          // 8192 rows
#define QKVLD 2304
#define SCALE 0.125f        // 64^-0.5

// ---------------- scratch (device globals: allocation-guard safe) ------------
__device__ float g_qkv[(size_t)NM * QKVLD];         // qkv fp32 (attention input)
__device__ float g_x2[(size_t)NM * NDIM];           // residual stream after attn
__device__ __nv_bfloat16 g_ahi[(size_t)NM * NDIM];  // activation hi plane (768 cols)
__device__ __nv_bfloat16 g_alo[(size_t)NM * NDIM];
__device__ __nv_bfloat16 g_bhi[(size_t)NM * NHID];  // mlp hidden hi plane
__device__ __nv_bfloat16 g_blo[(size_t)NM * NHID];
__device__ __nv_bfloat16 g_wqkv_hi[NDIM * QKVLD], g_wqkv_lo[NDIM * QKVLD];
__device__ __nv_bfloat16 g_wproj_hi[NDIM * NDIM],  g_wproj_lo[NDIM * NDIM];
__device__ __nv_bfloat16 g_w1_hi[NDIM * NHID],     g_w1_lo[NDIM * NHID];
__device__ __nv_bfloat16 g_w2_hi[NHID * NDIM],     g_w2_lo[NHID * NDIM];

// ---------------- PTX helpers -------------------------------------------------
__device__ __forceinline__ uint32_t smem_u32(const void* p) {
    uint32_t a;
    asm("{ .reg .u64 t; cvta.to.shared.u64 t, %1; cvt.u32.u64 %0, t; }" : "=r"(a) : "l"(p));
    return a;
}
__device__ __forceinline__ void cp16(uint32_t dst, const void* src) {
    asm volatile("cp.async.cg.shared.global [%0], [%1], 16;" :: "r"(dst), "l"(src) : "memory");
}
#define CP_COMMIT() asm volatile("cp.async.commit_group;" ::: "memory")
template <int N> __device__ __forceinline__ void cp_wait() {
    asm volatile("cp.async.wait_group %0;" :: "n"(N) : "memory");
}
__device__ __forceinline__ void ldm_x4(uint32_t* r, uint32_t addr) {
    asm volatile("ldmatrix.sync.aligned.m8n8.x4.shared.b16 {%0,%1,%2,%3}, [%4];"
        : "=r"(r[0]), "=r"(r[1]), "=r"(r[2]), "=r"(r[3]) : "r"(addr));
}
__device__ __forceinline__ void ldm_x2t(uint32_t* r, uint32_t addr) {
    asm volatile("ldmatrix.sync.aligned.m8n8.x2.trans.shared.b16 {%0,%1}, [%2];"
        : "=r"(r[0]), "=r"(r[1]) : "r"(addr));
}
__device__ __forceinline__ void mma16816(float* c, const uint32_t* a, const uint32_t* b) {
    asm volatile("mma.sync.aligned.m16n8k16.row.col.f32.bf16.bf16.f32 "
        "{%0,%1,%2,%3}, {%4,%5,%6,%7}, {%8,%9}, {%0,%1,%2,%3};"
        : "+f"(c[0]), "+f"(c[1]), "+f"(c[2]), "+f"(c[3])
        : "r"(a[0]), "r"(a[1]), "r"(a[2]), "r"(a[3]), "r"(b[0]), "r"(b[1]));
}

// ---------------- fp32 -> (hi,lo) bf16 split ---------------------------------
__device__ __forceinline__ void split2(float v, __nv_bfloat16& h, __nv_bfloat16& l) {
    h = __float2bfloat16(v);
    l = __float2bfloat16(v - __bfloat162float(h));
}

__global__ __launch_bounds__(256)
void split_kernel(const float* __restrict__ s, __nv_bfloat16* __restrict__ hi,
                  __nv_bfloat16* __restrict__ lo, int n4) {
    int i = blockIdx.x * 256 + threadIdx.x;
    if (i >= n4) return;
    float4 v = ((const float4*)s)[i];
    __nv_bfloat16 h0, h1, h2, h3, l0, l1, l2, l3;
    split2(v.x, h0, l0); split2(v.y, h1, l1); split2(v.z, h2, l2); split2(v.w, h3, l3);
    uint2 hw, lw;
    hw.x = (uint32_t)__bfloat16_as_ushort(h0) | ((uint32_t)__bfloat16_as_ushort(h1) << 16);
    hw.y = (uint32_t)__bfloat16_as_ushort(h2) | ((uint32_t)__bfloat16_as_ushort(h3) << 16);
    lw.x = (uint32_t)__bfloat16_as_ushort(l0) | ((uint32_t)__bfloat16_as_ushort(l1) << 16);
    lw.y = (uint32_t)__bfloat16_as_ushort(l2) | ((uint32_t)__bfloat16_as_ushort(l3) << 16);
    ((uint2*)hi)[i] = hw;
    ((uint2*)lo)[i] = lw;
}

// ---------------- LayerNorm -> split bf16 planes -----------------------------
__global__ __launch_bounds__(256)
void ln_split_kernel(const float* __restrict__ x, const float* __restrict__ g,
                     const float* __restrict__ be,
                     __nv_bfloat16* __restrict__ hi, __nv_bfloat16* __restrict__ lo) {
    int row = blockIdx.x;
    const float* xr = x + (size_t)row * NDIM;
    int tid = threadIdx.x;
    float v0 = xr[tid], v1 = xr[tid + 256], v2 = xr[tid + 512];
    float s  = v0 + v1 + v2;
    float s2 = v0 * v0 + v1 * v1 + v2 * v2;
#pragma unroll
    for (int o = 16; o; o >>= 1) {
        s  += __shfl_xor_sync(0xffffffffu, s,  o);
        s2 += __shfl_xor_sync(0xffffffffu, s2, o);
    }
    __shared__ float rs[8], rs2[8];
    int w = tid >> 5, ln = tid & 31;
    if (ln == 0) { rs[w] = s; rs2[w] = s2; }
    __syncthreads();
    if (w == 0) {
        s  = (ln < 8) ? rs[ln]  : 0.f;
        s2 = (ln < 8) ? rs2[ln] : 0.f;
#pragma unroll
        for (int o = 4; o; o >>= 1) {
            s  += __shfl_xor_sync(0xffffffffu, s,  o);
            s2 += __shfl_xor_sync(0xffffffffu, s2, o);
        }
        if (ln == 0) { rs[0] = s; rs2[0] = s2; }
    }
    __syncthreads();
    float mu  = rs[0] * (1.0f / NDIM);
    float var = rs2[0] * (1.0f / NDIM) - mu * mu;
    float inv = rsqrtf(var + 1e-6f);
    size_t ro = (size_t)row * NDIM;
#pragma unroll
    for (int t = 0; t < 3; t++) {
        int c = tid + t * 256;
        float v = (t == 0 ? v0 : (t == 1 ? v1 : v2));
        float y = (v - mu) * inv * g[c] + be[c];
        __nv_bfloat16 h, l;
        split2(y, h, l);
        hi[ro + c] = h;
        lo[ro + c] = l;
    }
}

// ---------------- HMMA split-bf16 GEMM ---------------------------------------
// C[M,N] = A[M,K] @ B[K,N] + epilogue. A row-major [M,K], B row-major [K,N],
// both as (hi,lo) bf16 planes. Split: Ahi*Bhi + Ahi*Blo + Alo*Bhi, fp32 acc.
// EPI: 0 = +bias -> fp32 ; 1 = +bias +res -> fp32 ; 2 = +bias, gelu -> planes
#define BK 32
#define A_ROWB 80            // 32 bf16 = 64B padded to 80B (conflict-free ldmatrix)
#define B_ROWB 272           // 128 bf16 = 256B padded to 272B
#define A_PLANE (128 * A_ROWB)      // 10240
#define B_PLANE (BK * B_ROWB)       // 8704
#define OFF_BHI (2 * A_PLANE)       // 20480
#define OFF_BLO (OFF_BHI + B_PLANE) // 29184
#define STAGE_BYTES (OFF_BLO + B_PLANE)  // 37888
#define GEMM_SMEM (3 * STAGE_BYTES)      // 113664

__device__ __forceinline__ void load_stage(
    uint32_t s, const __nv_bfloat16* __restrict__ Ahi, const __nv_bfloat16* __restrict__ Alo,
    const __nv_bfloat16* __restrict__ Bhi, const __nv_bfloat16* __restrict__ Blo,
    int lda, int ldb, size_t mbase, int nbase, int k0, int tid)
{
#pragma unroll
    for (int t = 0; t < 2; t++) {          // A: 128 rows x 64B = 512 cp16 / plane
        int idx = tid + t * 256;
        int row = idx >> 2, cc = idx & 3;
        uint32_t so = s + row * A_ROWB + cc * 16;
        size_t go = (mbase + row) * (size_t)lda + k0 + cc * 8;
        cp16(so,           Ahi + go);
        cp16(so + A_PLANE, Alo + go);
    }
#pragma unroll
    for (int t = 0; t < 2; t++) {          // B: 32 rows x 256B = 512 cp16 / plane
        int idx = tid + t * 256;
        int row = idx >> 4, cc = idx & 15;
        uint32_t so = s + OFF_BHI + row * B_ROWB + cc * 16;
        size_t go = (size_t)(k0 + row) * ldb + nbase + cc * 8;
        cp16(so,           Bhi + go);
        cp16(so + B_PLANE, Blo + go);
    }
}

template <int EPI>
__global__ __launch_bounds__(256, 1)
void hmma_gemm(const __nv_bfloat16* __restrict__ Ahi, const __nv_bfloat16* __restrict__ Alo,
               const __nv_bfloat16* __restrict__ Bhi, const __nv_bfloat16* __restrict__ Blo,
               const float* __restrict__ bias, const float* __restrict__ res,
               float* __restrict__ C, __nv_bfloat16* __restrict__ Chi,
               __nv_bfloat16* __restrict__ Clo, int N, int K)
{
    extern __shared__ char smem[];
    const uint32_t sbase = smem_u32(smem);
    const int tid = threadIdx.x;
    const int lane = tid & 31, wid = tid >> 5;
    const int wm = (wid & 1) * 64;     // warp m offset within CTA tile
    const int wn = (wid >> 1) * 32;    // warp n offset
    const size_t mbase = (size_t)blockIdx.y * 128;
    const int nbase = blockIdx.x * 128;
    const int lda = K, ldb = N;

    float acc[4][4][4];
#pragma unroll
    for (int mi = 0; mi < 4; mi++)
#pragma unroll
        for (int ni = 0; ni < 4; ni++)
#pragma unroll
            for (int q = 0; q < 4; q++) acc[mi][ni][q] = 0.f;

    // ldmatrix per-lane addressing
    const int a_row = wm + ((lane >> 3) & 1) * 8 + (lane & 7);  // + mi*16
    const int a_k   = ((lane >> 4) & 1) * 8;                    // + ks*16
    const int bl    = lane & 15;
    const int b_k   = (bl & 7) + ((bl >> 3) & 1) * 8;           // + ks*16

    const int NC = K / BK;
    load_stage(sbase,               Ahi, Alo, Bhi, Blo, lda, ldb, mbase, nbase, 0,  tid); CP_COMMIT();
    load_stage(sbase + STAGE_BYTES, Ahi, Alo, Bhi, Blo, lda, ldb, mbase, nbase, BK, tid); CP_COMMIT();

    for (int i = 0; i < NC; i++) {
        if (i + 1 < NC) cp_wait<1>(); else cp_wait<0>();
        __syncthreads();
        if (i + 2 < NC) {
            load_stage(sbase + ((i + 2) % 3) * STAGE_BYTES, Ahi, Alo, Bhi, Blo,
                       lda, ldb, mbase, nbase, (i + 2) * BK, tid);
            CP_COMMIT();
        }
        const uint32_t st = sbase + (i % 3) * STAGE_BYTES;
#pragma unroll
        for (int ks = 0; ks < 2; ks++) {
            uint32_t Ah[4][4], Al[4][4];
#pragma unroll
            for (int mi = 0; mi < 4; mi++) {
                uint32_t off = (uint32_t)((a_row + mi * 16) * A_ROWB + (a_k + ks * 16) * 2);
                ldm_x4(Ah[mi], st + off);
                ldm_x4(Al[mi], st + A_PLANE + off);
            }
            uint32_t Bh[4][2], Blr[4][2];
#pragma unroll
            for (int ni = 0; ni < 4; ni++) {
                uint32_t off = (uint32_t)((b_k + ks * 16) * B_ROWB + (wn + ni * 8) * 2);
                ldm_x2t(Bh[ni],  st + OFF_BHI + off);
                ldm_x2t(Blr[ni], st + OFF_BLO + off);
            }
#pragma unroll
            for (int mi = 0; mi < 4; mi++)
#pragma unroll
                for (int ni = 0; ni < 4; ni++) {
                    mma16816(acc[mi][ni], Ah[mi], Bh[ni]);
                    mma16816(acc[mi][ni], Ah[mi], Blr[ni]);
                    mma16816(acc[mi][ni], Al[mi], Bh[ni]);
                }
        }
    }

    // epilogue: c0,c1 -> (row, col..col+1) ; c2,c3 -> (row+8, ...)
    const int gid = lane >> 2, q4 = lane & 3;
#pragma unroll
    for (int mi = 0; mi < 4; mi++) {
        size_t r0 = mbase + wm + mi * 16 + gid;
#pragma unroll
        for (int half = 0; half < 2; half++) {
            size_t r = r0 + half * 8;
#pragma unroll
            for (int ni = 0; ni < 4; ni++) {
                int c = nbase + wn + ni * 8 + q4 * 2;
                float v0 = acc[mi][ni][half * 2 + 0] + bias[c];
                float v1 = acc[mi][ni][half * 2 + 1] + bias[c + 1];
                if (EPI == 1) {
                    const float2 rr = *(const float2*)(res + r * (size_t)N + c);
                    v0 += rr.x; v1 += rr.y;
                }
                if (EPI == 2) {
                    v0 = 0.5f * v0 * (1.0f + erff(v0 * 0.70710678118654752f));
                    v1 = 0.5f * v1 * (1.0f + erff(v1 * 0.70710678118654752f));
                    __nv_bfloat16 h0, h1, l0, l1;
                    split2(v0, h0, l0); split2(v1, h1, l1);
                    uint32_t hp = (uint32_t)__bfloat16_as_ushort(h0) | ((uint32_t)__bfloat16_as_ushort(h1) << 16);
                    uint32_t lp = (uint32_t)__bfloat16_as_ushort(l0) | ((uint32_t)__bfloat16_as_ushort(l1) << 16);
                    *(uint32_t*)(Chi + r * (size_t)N + c) = hp;
                    *(uint32_t*)(Clo + r * (size_t)N + c) = lp;
                } else {
                    float2 v; v.x = v0; v.y = v1;
                    *(float2*)(C + r * (size_t)N + c) = v;
                }
            }
        }
    }
}

// ---------------- Attention: online-softmax, writes split bf16 planes --------
__global__ __launch_bounds__(128)
void attn_kernel(const float* __restrict__ qkv, const int* __restrict__ mask,
                 __nv_bfloat16* __restrict__ ohi, __nv_bfloat16* __restrict__ olo) {
    constexpr int TK = 16;
    const int q0 = blockIdx.x * 128;
    const int h  = blockIdx.y;
    const int b  = blockIdx.z;
    const int tid = threadIdx.x;

    __shared__ __align__(16) float q_s[128][68];
    __shared__ __align__(16) float k_s[TK][64];
    __shared__ __align__(16) float v_s[TK][64];

    const float* qbase = qkv + (size_t)(b * NS + q0) * QKVLD + h * HD;
#pragma unroll
    for (int it = 0; it < 16; it++) {
        int i = tid + it * 128;
        int r = i >> 4, c4 = (i & 15) * 4;
        *(float4*)&q_s[r][c4] = *(const float4*)(qbase + (size_t)r * QKVLD + c4);
    }

    const float* kbase = qkv + (size_t)b * NS * QKVLD + NDIM + h * HD;
    const float* vbase = kbase + NDIM;
    const int* mrow = mask + (size_t)b * NS * NS + (size_t)(q0 + tid) * NS;

    float mx = -1e30f, l = 0.f;
    float acc[HD];
#pragma unroll
    for (int d = 0; d < HD; d++) acc[d] = 0.f;

    for (int k0 = 0; k0 < NS; k0 += TK) {
        __syncthreads();
        {
            int i0 = tid, i1 = tid + 128;
            int r0 = i0 >> 4, c0 = (i0 & 15) * 4;
            int r1 = i1 >> 4, c1 = (i1 & 15) * 4;
            *(float4*)&k_s[r0][c0] = *(const float4*)(kbase + (size_t)(k0 + r0) * QKVLD + c0);
            *(float4*)&k_s[r1][c1] = *(const float4*)(kbase + (size_t)(k0 + r1) * QKVLD + c1);
            *(float4*)&v_s[r0][c0] = *(const float4*)(vbase + (size_t)(k0 + r0) * QKVLD + c0);
            *(float4*)&v_s[r1][c1] = *(const float4*)(vbase + (size_t)(k0 + r1) * QKVLD + c1);
        }
        __syncthreads();

        float s[TK];
#pragma unroll
        for (int kk = 0; kk < TK; kk++) s[kk] = 0.f;
#pragma unroll
        for (int d4 = 0; d4 < 16; d4++) {
            float4 qv = *(const float4*)&q_s[tid][d4 * 4];
#pragma unroll
            for (int kk = 0; kk < TK; kk++) {
                float4 kv = *(const float4*)&k_s[kk][d4 * 4];
                s[kk] += qv.x * kv.x + qv.y * kv.y + qv.z * kv.z + qv.w * kv.w;
            }
        }
#pragma unroll
        for (int i4 = 0; i4 < TK / 4; i4++) {
            int4 mv = *(const int4*)(mrow + k0 + i4 * 4);
            s[i4 * 4 + 0] = (mv.x == 0) ? -10000.f : s[i4 * 4 + 0] * SCALE;
            s[i4 * 4 + 1] = (mv.y == 0) ? -10000.f : s[i4 * 4 + 1] * SCALE;
            s[i4 * 4 + 2] = (mv.z == 0) ? -10000.f : s[i4 * 4 + 2] * SCALE;
            s[i4 * 4 + 3] = (mv.w == 0) ? -10000.f : s[i4 * 4 + 3] * SCALE;
        }

        float tmax = -1e30f;
#pragma unroll
        for (int kk = 0; kk < TK; kk++) tmax = fmaxf(tmax, s[kk]);
        float nm = fmaxf(mx, tmax);
        float corr = __expf(mx - nm);
        l *= corr;
#pragma unroll
        for (int d = 0; d < HD; d++) acc[d] *= corr;
#pragma unroll
        for (int kk = 0; kk < TK; kk++) {
            float p = __expf(s[kk] - nm);
            l += p;
            s[kk] = p;
        }
#pragma unroll
        for (int kk = 0; kk < TK; kk++) {
            float p = s[kk];
#pragma unroll
            for (int d4 = 0; d4 < 16; d4++) {
                float4 vv = *(const float4*)&v_s[kk][d4 * 4];
                acc[d4 * 4 + 0] = fmaf(p, vv.x, acc[d4 * 4 + 0]);
                acc[d4 * 4 + 1] = fmaf(p, vv.y, acc[d4 * 4 + 1]);
                acc[d4 * 4 + 2] = fmaf(p, vv.z, acc[d4 * 4 + 2]);
                acc[d4 * 4 + 3] = fmaf(p, vv.w, acc[d4 * 4 + 3]);
            }
        }
        mx = nm;
    }

    float invl = 1.0f / l;
    size_t ro = (size_t)(b * NS + q0 + tid) * NDIM + h * HD;
#pragma unroll
    for (int d4 = 0; d4 < 16; d4++) {
        __nv_bfloat16 h0, h1, h2, h3, l0, l1, l2, l3;
        split2(acc[d4 * 4 + 0] * invl, h0, l0);
        split2(acc[d4 * 4 + 1] * invl, h1, l1);
        split2(acc[d4 * 4 + 2] * invl, h2, l2);
        split2(acc[d4 * 4 + 3] * invl, h3, l3);
        uint2 hw, lw;
        hw.x = (uint32_t)__bfloat16_as_ushort(h0) | ((uint32_t)__bfloat16_as_ushort(h1) << 16);
        hw.y = (uint32_t)__bfloat16_as_ushort(h2) | ((uint32_t)__bfloat16_as_ushort(h3) << 16);
        lw.x = (uint32_t)__bfloat16_as_ushort(l0) | ((uint32_t)__bfloat16_as_ushort(l1) << 16);
        lw.y = (uint32_t)__bfloat16_as_ushort(l2) | ((uint32_t)__bfloat16_as_ushort(l3) << 16);
        *(uint2*)(ohi + ro + d4 * 4) = hw;
        *(uint2*)(olo + ro + d4 * 4) = lw;
    }
}

// ---------------- launch ------------------------------------------------------
extern "C" void kernel_launch(void* const* d_in, const int* in_sizes, int n_in,
                              void* d_out, int out_size) {
    const float* x      = (const float*)d_in[0];
    const int*   mask   = (const int*)  d_in[1];
    const float* w_qkv  = (const float*)d_in[2];
    const float* b_qkv  = (const float*)d_in[3];
    const float* w_proj = (const float*)d_in[4];
    const float* b_proj = (const float*)d_in[5];
    const float* g1     = (const float*)d_in[6];
    const float* be1    = (const float*)d_in[7];
    const float* g2     = (const float*)d_in[8];
    const float* be2    = (const float*)d_in[9];
    const float* w1     = (const float*)d_in[10];
    const float* b1     = (const float*)d_in[11];
    const float* w2     = (const float*)d_in[12];
    const float* b2     = (const float*)d_in[13];
    float* out = (float*)d_out;

    float *qkv_p, *x2_p;
    __nv_bfloat16 *ahi, *alo, *bhi, *blo;
    __nv_bfloat16 *wqh, *wql, *wph, *wpl, *w1h, *w1l, *w2h, *w2l;
    cudaGetSymbolAddress((void**)&qkv_p, g_qkv);
    cudaGetSymbolAddress((void**)&x2_p,  g_x2);
    cudaGetSymbolAddress((void**)&ahi,   g_ahi);
    cudaGetSymbolAddress((void**)&alo,   g_alo);
    cudaGetSymbolAddress((void**)&bhi,   g_bhi);
    cudaGetSymbolAddress((void**)&blo,   g_blo);
    cudaGetSymbolAddress((void**)&wqh,   g_wqkv_hi);
    cudaGetSymbolAddress((void**)&wql,   g_wqkv_lo);
    cudaGetSymbolAddress((void**)&wph,   g_wproj_hi);
    cudaGetSymbolAddress((void**)&wpl,   g_wproj_lo);
    cudaGetSymbolAddress((void**)&w1h,   g_w1_hi);
    cudaGetSymbolAddress((void**)&w1l,   g_w1_lo);
    cudaGetSymbolAddress((void**)&w2h,   g_w2_hi);
    cudaGetSymbolAddress((void**)&w2l,   g_w2_lo);

    cudaFuncSetAttribute(hmma_gemm<0>, cudaFuncAttributeMaxDynamicSharedMemorySize, GEMM_SMEM);
    cudaFuncSetAttribute(hmma_gemm<1>, cudaFuncAttributeMaxDynamicSharedMemorySize, GEMM_SMEM);
    cudaFuncSetAttribute(hmma_gemm<2>, cudaFuncAttributeMaxDynamicSharedMemorySize, GEMM_SMEM);

    // weight splits
    {
        int n4;
        n4 = NDIM * QKVLD / 4; split_kernel<<<(n4 + 255) / 256, 256>>>(w_qkv,  wqh, wql, n4);
        n4 = NDIM * NDIM / 4;  split_kernel<<<(n4 + 255) / 256, 256>>>(w_proj, wph, wpl, n4);
        n4 = NDIM * NHID / 4;  split_kernel<<<(n4 + 255) / 256, 256>>>(w1,     w1h, w1l, n4);
        n4 = NHID * NDIM / 4;  split_kernel<<<(n4 + 255) / 256, 256>>>(w2,     w2h, w2l, n4);
    }

    // 1) LN1 -> split planes
    ln_split_kernel<<<NM, 256>>>(x, g1, be1, ahi, alo);
    // 2) qkv = h @ w_qkv + b_qkv   (fp32 out)
    hmma_gemm<0><<<dim3(QKVLD / 128, NM / 128), 256, GEMM_SMEM>>>(
        ahi, alo, wqh, wql, b_qkv, nullptr, qkv_p, nullptr, nullptr, QKVLD, NDIM);
    // 3) attention -> split planes
    attn_kernel<<<dim3(NS / 128, NH, NB), 128>>>(qkv_p, mask, ahi, alo);
    // 4) x2 = x + attn @ w_proj + b_proj
    hmma_gemm<1><<<dim3(NDIM / 128, NM / 128), 256, GEMM_SMEM>>>(
        ahi, alo, wph, wpl, b_proj, x, x2_p, nullptr, nullptr, NDIM, NDIM);
    // 5) LN2 -> split planes
    ln_split_kernel<<<NM, 256>>>(x2_p, g2, be2, ahi, alo);
    // 6) hid = gelu(h @ w1 + b1) -> split planes
    hmma_gemm<2><<<dim3(NHID / 128, NM / 128), 256, GEMM_SMEM>>>(
        ahi, alo, w1h, w1l, b1, nullptr, nullptr, bhi, blo, NHID, NDIM);
    // 7) out = x2 + hid @ w2 + b2
    hmma_gemm<1><<<dim3(NDIM / 128, NM / 128), 256, GEMM_SMEM>>>(
        bhi, blo, w2h, w2l, b2, x2_p, out, nullptr, nullptr, NDIM, NHID);
}

// round 8
// speedup vs baseline: 2.7427x; 1.8241x over previous
#include <cuda_runtime.h>
#include <cuda_bf16.h>
#include <cstdint>
#include <cstddef>

#define NB 4
#define NS 2048
#define NDIM 768
#define NH 12
#define HD 64
#define NHID 3072
#define NM (NB*NS)          // 8192 rows
#define QKVLD 2304
#define SCALE 0.125f        // 64^-0.5

// ---------------- scratch (device globals: allocation-guard safe) ------------
__device__ float g_x2[(size_t)NM * NDIM];           // residual stream after attn
__device__ __nv_bfloat16 g_ahi[(size_t)NM * NDIM];  // activation hi plane
__device__ __nv_bfloat16 g_alo[(size_t)NM * NDIM];
__device__ __nv_bfloat16 g_bhi[(size_t)NM * NHID];  // mlp hidden hi plane
__device__ __nv_bfloat16 g_blo[(size_t)NM * NHID];
// head-major qkv planes: [(b*NH+h)*NS + s]*64 + d
__device__ __nv_bfloat16 g_qhi[(size_t)NM * NDIM], g_qlo[(size_t)NM * NDIM];
__device__ __nv_bfloat16 g_khi[(size_t)NM * NDIM], g_klo[(size_t)NM * NDIM];
__device__ __nv_bfloat16 g_vhi[(size_t)NM * NDIM], g_vlo[(size_t)NM * NDIM];
__device__ uint32_t g_mbits[(size_t)NB * NS * (NS / 32)];
__device__ __nv_bfloat16 g_wqkv_hi[NDIM * QKVLD], g_wqkv_lo[NDIM * QKVLD];
__device__ __nv_bfloat16 g_wproj_hi[NDIM * NDIM],  g_wproj_lo[NDIM * NDIM];
__device__ __nv_bfloat16 g_w1_hi[NDIM * NHID],     g_w1_lo[NDIM * NHID];
__device__ __nv_bfloat16 g_w2_hi[NHID * NDIM],     g_w2_lo[NHID * NDIM];

// ---------------- PTX helpers -------------------------------------------------
__device__ __forceinline__ uint32_t smem_u32(const void* p) {
    uint32_t a;
    asm("{ .reg .u64 t; cvta.to.shared.u64 t, %1; cvt.u32.u64 %0, t; }" : "=r"(a) : "l"(p));
    return a;
}
__device__ __forceinline__ void cp16(uint32_t dst, const void* src) {
    asm volatile("cp.async.cg.shared.global [%0], [%1], 16;" :: "r"(dst), "l"(src) : "memory");
}
#define CP_COMMIT() asm volatile("cp.async.commit_group;" ::: "memory")
template <int N> __device__ __forceinline__ void cp_wait() {
    asm volatile("cp.async.wait_group %0;" :: "n"(N) : "memory");
}
__device__ __forceinline__ void ldm_x4(uint32_t* r, uint32_t addr) {
    asm volatile("ldmatrix.sync.aligned.m8n8.x4.shared.b16 {%0,%1,%2,%3}, [%4];"
        : "=r"(r[0]), "=r"(r[1]), "=r"(r[2]), "=r"(r[3]) : "r"(addr));
}
__device__ __forceinline__ void ldm_x2(uint32_t* r, uint32_t addr) {
    asm volatile("ldmatrix.sync.aligned.m8n8.x2.shared.b16 {%0,%1}, [%2];"
        : "=r"(r[0]), "=r"(r[1]) : "r"(addr));
}
__device__ __forceinline__ void ldm_x2t(uint32_t* r, uint32_t addr) {
    asm volatile("ldmatrix.sync.aligned.m8n8.x2.trans.shared.b16 {%0,%1}, [%2];"
        : "=r"(r[0]), "=r"(r[1]) : "r"(addr));
}
__device__ __forceinline__ void mma16816(float* c, const uint32_t* a, const uint32_t* b) {
    asm volatile("mma.sync.aligned.m16n8k16.row.col.f32.bf16.bf16.f32 "
        "{%0,%1,%2,%3}, {%4,%5,%6,%7}, {%8,%9}, {%0,%1,%2,%3};"
        : "+f"(c[0]), "+f"(c[1]), "+f"(c[2]), "+f"(c[3])
        : "r"(a[0]), "r"(a[1]), "r"(a[2]), "r"(a[3]), "r"(b[0]), "r"(b[1]));
}

// ---------------- fp32 -> (hi,lo) bf16 split ---------------------------------
__device__ __forceinline__ void split2(float v, __nv_bfloat16& h, __nv_bfloat16& l) {
    h = __float2bfloat16(v);
    l = __float2bfloat16(v - __bfloat162float(h));
}
__device__ __forceinline__ uint32_t packbf(__nv_bfloat16 a, __nv_bfloat16 b) {
    return (uint32_t)__bfloat16_as_ushort(a) | ((uint32_t)__bfloat16_as_ushort(b) << 16);
}

__global__ __launch_bounds__(256)
void split_kernel(const float* __restrict__ s, __nv_bfloat16* __restrict__ hi,
                  __nv_bfloat16* __restrict__ lo, int n4) {
    int i = blockIdx.x * 256 + threadIdx.x;
    if (i >= n4) return;
    float4 v = ((const float4*)s)[i];
    __nv_bfloat16 h0, h1, h2, h3, l0, l1, l2, l3;
    split2(v.x, h0, l0); split2(v.y, h1, l1); split2(v.z, h2, l2); split2(v.w, h3, l3);
    ((uint2*)hi)[i] = make_uint2(packbf(h0, h1), packbf(h2, h3));
    ((uint2*)lo)[i] = make_uint2(packbf(l0, l1), packbf(l2, l3));
}

// ---------------- mask -> bitmask --------------------------------------------
__global__ __launch_bounds__(256)
void pack_mask_kernel(const int* __restrict__ mask, uint32_t* __restrict__ bits) {
    int w = blockIdx.x * 256 + threadIdx.x;   // total NB*NS*64 words
    const int4* src = (const int4*)(mask + (size_t)w * 32);
    uint32_t v = 0;
#pragma unroll
    for (int c = 0; c < 8; c++) {
        int4 m = src[c];
        if (m.x) v |= 1u << (c * 4 + 0);
        if (m.y) v |= 1u << (c * 4 + 1);
        if (m.z) v |= 1u << (c * 4 + 2);
        if (m.w) v |= 1u << (c * 4 + 3);
    }
    bits[w] = v;
}

// ---------------- LayerNorm -> split bf16 planes -----------------------------
__global__ __launch_bounds__(256)
void ln_split_kernel(const float* __restrict__ x, const float* __restrict__ g,
                     const float* __restrict__ be,
                     __nv_bfloat16* __restrict__ hi, __nv_bfloat16* __restrict__ lo) {
    int row = blockIdx.x;
    const float* xr = x + (size_t)row * NDIM;
    int tid = threadIdx.x;
    float v0 = xr[tid], v1 = xr[tid + 256], v2 = xr[tid + 512];
    float s  = v0 + v1 + v2;
    float s2 = v0 * v0 + v1 * v1 + v2 * v2;
#pragma unroll
    for (int o = 16; o; o >>= 1) {
        s  += __shfl_xor_sync(0xffffffffu, s,  o);
        s2 += __shfl_xor_sync(0xffffffffu, s2, o);
    }
    __shared__ float rs[8], rs2[8];
    int w = tid >> 5, ln = tid & 31;
    if (ln == 0) { rs[w] = s; rs2[w] = s2; }
    __syncthreads();
    if (w == 0) {
        s  = (ln < 8) ? rs[ln]  : 0.f;
        s2 = (ln < 8) ? rs2[ln] : 0.f;
#pragma unroll
        for (int o = 4; o; o >>= 1) {
            s  += __shfl_xor_sync(0xffffffffu, s,  o);
            s2 += __shfl_xor_sync(0xffffffffu, s2, o);
        }
        if (ln == 0) { rs[0] = s; rs2[0] = s2; }
    }
    __syncthreads();
    float mu  = rs[0] * (1.0f / NDIM);
    float var = rs2[0] * (1.0f / NDIM) - mu * mu;
    float inv = rsqrtf(var + 1e-6f);
    size_t ro = (size_t)row * NDIM;
#pragma unroll
    for (int t = 0; t < 3; t++) {
        int c = tid + t * 256;
        float v = (t == 0 ? v0 : (t == 1 ? v1 : v2));
        float y = (v - mu) * inv * g[c] + be[c];
        __nv_bfloat16 h, l;
        split2(y, h, l);
        hi[ro + c] = h;
        lo[ro + c] = l;
    }
}

// ---------------- HMMA split-bf16 GEMM ---------------------------------------
// EPI: 0=+bias->fp32 ; 1=+bias+res->fp32 ; 2=+bias,gelu->planes ;
//      3=+bias -> head-major qkv (hi,lo) planes
#define BK 32
#define A_ROWB 80
#define B_ROWB 272
#define A_PLANE (128 * A_ROWB)
#define B_PLANE (BK * B_ROWB)
#define OFF_BHI (2 * A_PLANE)
#define OFF_BLO (OFF_BHI + B_PLANE)
#define STAGE_BYTES (OFF_BLO + B_PLANE)
#define GEMM_SMEM (3 * STAGE_BYTES)

__device__ __forceinline__ void load_stage(
    uint32_t s, const __nv_bfloat16* __restrict__ Ahi, const __nv_bfloat16* __restrict__ Alo,
    const __nv_bfloat16* __restrict__ Bhi, const __nv_bfloat16* __restrict__ Blo,
    int lda, int ldb, size_t mbase, int nbase, int k0, int tid)
{
#pragma unroll
    for (int t = 0; t < 2; t++) {
        int idx = tid + t * 256;
        int row = idx >> 2, cc = idx & 3;
        uint32_t so = s + row * A_ROWB + cc * 16;
        size_t go = (mbase + row) * (size_t)lda + k0 + cc * 8;
        cp16(so,           Ahi + go);
        cp16(so + A_PLANE, Alo + go);
    }
#pragma unroll
    for (int t = 0; t < 2; t++) {
        int idx = tid + t * 256;
        int row = idx >> 4, cc = idx & 15;
        uint32_t so = s + OFF_BHI + row * B_ROWB + cc * 16;
        size_t go = (size_t)(k0 + row) * ldb + nbase + cc * 8;
        cp16(so,           Bhi + go);
        cp16(so + B_PLANE, Blo + go);
    }
}

template <int EPI>
__global__ __launch_bounds__(256, 1)
void hmma_gemm(const __nv_bfloat16* __restrict__ Ahi, const __nv_bfloat16* __restrict__ Alo,
               const __nv_bfloat16* __restrict__ Bhi, const __nv_bfloat16* __restrict__ Blo,
               const float* __restrict__ bias, const float* __restrict__ res,
               float* __restrict__ C, __nv_bfloat16* __restrict__ Chi,
               __nv_bfloat16* __restrict__ Clo,
               __nv_bfloat16* __restrict__ Dhi, __nv_bfloat16* __restrict__ Dlo,
               __nv_bfloat16* __restrict__ Ehi, __nv_bfloat16* __restrict__ Elo,
               int N, int K)
{
    extern __shared__ char smem[];
    const uint32_t sbase = smem_u32(smem);
    const int tid = threadIdx.x;
    const int lane = tid & 31, wid = tid >> 5;
    const int wm = (wid & 1) * 64;
    const int wn = (wid >> 1) * 32;
    const size_t mbase = (size_t)blockIdx.y * 128;
    const int nbase = blockIdx.x * 128;
    const int lda = K, ldb = N;

    float acc[4][4][4];
#pragma unroll
    for (int mi = 0; mi < 4; mi++)
#pragma unroll
        for (int ni = 0; ni < 4; ni++)
#pragma unroll
            for (int q = 0; q < 4; q++) acc[mi][ni][q] = 0.f;

    const int a_row = wm + ((lane >> 3) & 1) * 8 + (lane & 7);
    const int a_k   = ((lane >> 4) & 1) * 8;
    const int bl    = lane & 15;
    const int b_k   = (bl & 7) + ((bl >> 3) & 1) * 8;

    const int NC = K / BK;
    load_stage(sbase,               Ahi, Alo, Bhi, Blo, lda, ldb, mbase, nbase, 0,  tid); CP_COMMIT();
    load_stage(sbase + STAGE_BYTES, Ahi, Alo, Bhi, Blo, lda, ldb, mbase, nbase, BK, tid); CP_COMMIT();

    for (int i = 0; i < NC; i++) {
        if (i + 1 < NC) cp_wait<1>(); else cp_wait<0>();
        __syncthreads();
        if (i + 2 < NC) {
            load_stage(sbase + ((i + 2) % 3) * STAGE_BYTES, Ahi, Alo, Bhi, Blo,
                       lda, ldb, mbase, nbase, (i + 2) * BK, tid);
            CP_COMMIT();
        }
        const uint32_t st = sbase + (i % 3) * STAGE_BYTES;
#pragma unroll
        for (int ks = 0; ks < 2; ks++) {
            uint32_t Ah[4][4], Al[4][4];
#pragma unroll
            for (int mi = 0; mi < 4; mi++) {
                uint32_t off = (uint32_t)((a_row + mi * 16) * A_ROWB + (a_k + ks * 16) * 2);
                ldm_x4(Ah[mi], st + off);
                ldm_x4(Al[mi], st + A_PLANE + off);
            }
            uint32_t Bh[4][2], Blr[4][2];
#pragma unroll
            for (int ni = 0; ni < 4; ni++) {
                uint32_t off = (uint32_t)((b_k + ks * 16) * B_ROWB + (wn + ni * 8) * 2);
                ldm_x2t(Bh[ni],  st + OFF_BHI + off);
                ldm_x2t(Blr[ni], st + OFF_BLO + off);
            }
#pragma unroll
            for (int mi = 0; mi < 4; mi++)
#pragma unroll
                for (int ni = 0; ni < 4; ni++) {
                    mma16816(acc[mi][ni], Ah[mi], Bh[ni]);
                    mma16816(acc[mi][ni], Ah[mi], Blr[ni]);
                    mma16816(acc[mi][ni], Al[mi], Bh[ni]);
                }
        }
    }

    const int gid = lane >> 2, q4 = lane & 3;
#pragma unroll
    for (int mi = 0; mi < 4; mi++) {
        size_t r0 = mbase + wm + mi * 16 + gid;
#pragma unroll
        for (int half = 0; half < 2; half++) {
            size_t r = r0 + half * 8;
#pragma unroll
            for (int ni = 0; ni < 4; ni++) {
                int c = nbase + wn + ni * 8 + q4 * 2;
                float v0 = acc[mi][ni][half * 2 + 0] + bias[c];
                float v1 = acc[mi][ni][half * 2 + 1] + bias[c + 1];
                if (EPI == 0) {
                    float2 v; v.x = v0; v.y = v1;
                    *(float2*)(C + r * (size_t)N + c) = v;
                } else if (EPI == 1) {
                    const float2 rr = *(const float2*)(res + r * (size_t)N + c);
                    float2 v; v.x = v0 + rr.x; v.y = v1 + rr.y;
                    *(float2*)(C + r * (size_t)N + c) = v;
                } else if (EPI == 2) {
                    v0 = 0.5f * v0 * (1.0f + erff(v0 * 0.70710678118654752f));
                    v1 = 0.5f * v1 * (1.0f + erff(v1 * 0.70710678118654752f));
                    __nv_bfloat16 h0, h1, l0, l1;
                    split2(v0, h0, l0); split2(v1, h1, l1);
                    *(uint32_t*)(Chi + r * (size_t)N + c) = packbf(h0, h1);
                    *(uint32_t*)(Clo + r * (size_t)N + c) = packbf(l0, l1);
                } else {
                    // EPI 3: head-major qkv planes
                    int which = c / NDIM;
                    int rem = c - which * NDIM;
                    int head = rem >> 6, d = rem & 63;
                    size_t dst = (((r >> 11) * NH + head) * (size_t)NS + (r & 2047)) * HD + d;
                    __nv_bfloat16 h0, h1, l0, l1;
                    split2(v0, h0, l0); split2(v1, h1, l1);
                    __nv_bfloat16* ph = (which == 0) ? Chi : (which == 1) ? Dhi : Ehi;
                    __nv_bfloat16* pl = (which == 0) ? Clo : (which == 1) ? Dlo : Elo;
                    *(uint32_t*)(ph + dst) = packbf(h0, h1);
                    *(uint32_t*)(pl + dst) = packbf(l0, l1);
                }
            }
        }
    }
}

// ---------------- HMMA flash attention ---------------------------------------
// grid (NS/128, NH, NB), 256 threads = 8 warps x 16 q-rows.
// K/V chunks of 64 keys double-buffered; split-bf16 QK and PV.
#define AT_ROWB 144
#define AT_QPLANE (128 * AT_ROWB)            // 18432
#define AT_KV (64 * AT_ROWB)                 // 9216
#define AT_BUF (4 * AT_KV)                   // 36864
#define AT_BUF0 (2 * AT_QPLANE)              // 36864
#define ATTN_SMEM (2 * AT_QPLANE + 2 * AT_BUF)  // 110592

__device__ __forceinline__ void attn_load_kv(
    uint32_t buf, const __nv_bfloat16* __restrict__ khi, const __nv_bfloat16* __restrict__ klo,
    const __nv_bfloat16* __restrict__ vhi, const __nv_bfloat16* __restrict__ vlo,
    size_t hb, int k0, int tid)
{
#pragma unroll
    for (int t = 0; t < 2; t++) {
        int idx = tid + t * 256;
        int row = idx >> 3, cc = idx & 7;
        uint32_t so = buf + row * AT_ROWB + cc * 16;
        size_t go = hb + (size_t)(k0 + row) * HD + cc * 8;
        cp16(so,              khi + go);
        cp16(so + AT_KV,      klo + go);
        cp16(so + 2 * AT_KV,  vhi + go);
        cp16(so + 3 * AT_KV,  vlo + go);
    }
}

__global__ __launch_bounds__(256, 1)
void attn_hmma(const __nv_bfloat16* __restrict__ qhi, const __nv_bfloat16* __restrict__ qlo,
               const __nv_bfloat16* __restrict__ khi, const __nv_bfloat16* __restrict__ klo,
               const __nv_bfloat16* __restrict__ vhi, const __nv_bfloat16* __restrict__ vlo,
               const uint32_t* __restrict__ mbits,
               __nv_bfloat16* __restrict__ ohi, __nv_bfloat16* __restrict__ olo)
{
    extern __shared__ char smem[];
    const uint32_t sbase = smem_u32(smem);
    const int tid = threadIdx.x;
    const int lane = tid & 31, wid = tid >> 5;
    const int gid = lane >> 2, q4 = lane & 3;
    const int q0 = blockIdx.x * 128;
    const int h  = blockIdx.y;
    const int b  = blockIdx.z;
    const size_t hb = ((size_t)b * NH + h) * NS * HD;

    // stage Q tile (128 rows x 64 d, hi+lo)
#pragma unroll
    for (int t = 0; t < 4; t++) {
        int idx = tid + t * 256;
        int row = idx >> 3, cc = idx & 7;
        uint32_t so = sbase + row * AT_ROWB + cc * 16;
        size_t go = hb + (size_t)(q0 + row) * HD + cc * 8;
        cp16(so,             qhi + go);
        cp16(so + AT_QPLANE, qlo + go);
    }
    CP_COMMIT();
    // prologue KV chunk 0
    attn_load_kv(sbase + AT_BUF0, khi, klo, vhi, vlo, hb, 0, tid);
    CP_COMMIT();
    cp_wait<1>();  // Q ready
    __syncthreads();

    // Q frags (16 rows per warp)
    uint32_t qh[4][4], ql[4][4];
    {
        const int a_row = wid * 16 + ((lane >> 3) & 1) * 8 + (lane & 7);
        const int a_k   = ((lane >> 4) & 1) * 8;
#pragma unroll
        for (int ks = 0; ks < 4; ks++) {
            uint32_t off = (uint32_t)(a_row * AT_ROWB + (a_k + ks * 16) * 2);
            ldm_x4(qh[ks], sbase + off);
            ldm_x4(ql[ks], sbase + AT_QPLANE + off);
        }
    }

    float o[8][4];
#pragma unroll
    for (int nf = 0; nf < 8; nf++)
#pragma unroll
        for (int q = 0; q < 4; q++) o[nf][q] = 0.f;
    float m0 = -1e30f, m1 = -1e30f, l0 = 0.f, l1 = 0.f;

    const int r0 = q0 + wid * 16 + gid;
    const uint32_t* mrow0 = mbits + ((size_t)b * NS + r0) * 64;
    const uint32_t* mrow1 = mrow0 + 8 * 64;

    // ldmatrix lane addressing for B-frags
    const int bl = lane & 15;
    const int qk_key = (bl & 7);                 // + nf*8
    const int qk_d   = ((bl >> 3) & 1) * 8;      // + ks*16
    const int pv_key = (bl & 7) + ((bl >> 3) & 1) * 8;  // + kk*16
    // pv d offset = nf*8

    for (int it = 0; it < 32; it++) {
        const uint32_t buf = sbase + AT_BUF0 + (it & 1) * AT_BUF;
        if (it + 1 < 32) {
            attn_load_kv(sbase + AT_BUF0 + ((it + 1) & 1) * AT_BUF,
                         khi, klo, vhi, vlo, hb, (it + 1) * 64, tid);
            CP_COMMIT();
            cp_wait<1>();
        } else {
            cp_wait<0>();
        }
        __syncthreads();

        // ---- S = Q K^T (split) ----
        float s[8][4];
#pragma unroll
        for (int nf = 0; nf < 8; nf++)
#pragma unroll
            for (int q = 0; q < 4; q++) s[nf][q] = 0.f;
#pragma unroll
        for (int nf = 0; nf < 8; nf++) {
#pragma unroll
            for (int ks = 0; ks < 4; ks++) {
                uint32_t off = (uint32_t)((nf * 8 + qk_key) * AT_ROWB + (qk_d + ks * 16) * 2);
                uint32_t bh[2], blr[2];
                ldm_x2(bh,  buf + off);
                ldm_x2(blr, buf + AT_KV + off);
                mma16816(s[nf], qh[ks], bh);
                mma16816(s[nf], qh[ks], blr);
                mma16816(s[nf], ql[ks], bh);
            }
        }

        // ---- mask + scale ----
        const uint2 mw0 = *(const uint2*)(mrow0 + it * 2);
        const uint2 mw1 = *(const uint2*)(mrow1 + it * 2);
#pragma unroll
        for (int nf = 0; nf < 8; nf++) {
            const int sh = (nf & 3) * 8 + q4 * 2;
            const uint32_t w0 = (nf < 4) ? mw0.x : mw0.y;
            const uint32_t w1 = (nf < 4) ? mw1.x : mw1.y;
            s[nf][0] = ((w0 >> sh) & 1u)       ? s[nf][0] * SCALE : -10000.f;
            s[nf][1] = ((w0 >> (sh + 1)) & 1u) ? s[nf][1] * SCALE : -10000.f;
            s[nf][2] = ((w1 >> sh) & 1u)       ? s[nf][2] * SCALE : -10000.f;
            s[nf][3] = ((w1 >> (sh + 1)) & 1u) ? s[nf][3] * SCALE : -10000.f;
        }

        // ---- online softmax ----
        float rx0 = -1e30f, rx1 = -1e30f;
#pragma unroll
        for (int nf = 0; nf < 8; nf++) {
            rx0 = fmaxf(rx0, fmaxf(s[nf][0], s[nf][1]));
            rx1 = fmaxf(rx1, fmaxf(s[nf][2], s[nf][3]));
        }
        rx0 = fmaxf(rx0, __shfl_xor_sync(0xffffffffu, rx0, 1));
        rx0 = fmaxf(rx0, __shfl_xor_sync(0xffffffffu, rx0, 2));
        rx1 = fmaxf(rx1, __shfl_xor_sync(0xffffffffu, rx1, 1));
        rx1 = fmaxf(rx1, __shfl_xor_sync(0xffffffffu, rx1, 2));
        const float nm0 = fmaxf(m0, rx0), nm1 = fmaxf(m1, rx1);
        const float c0 = __expf(m0 - nm0), c1 = __expf(m1 - nm1);
        l0 *= c0; l1 *= c1;
#pragma unroll
        for (int nf = 0; nf < 8; nf++) {
            o[nf][0] *= c0; o[nf][1] *= c0;
            o[nf][2] *= c1; o[nf][3] *= c1;
        }
#pragma unroll
        for (int nf = 0; nf < 8; nf++) {
            float p0 = __expf(s[nf][0] - nm0);
            float p1 = __expf(s[nf][1] - nm0);
            float p2 = __expf(s[nf][2] - nm1);
            float p3 = __expf(s[nf][3] - nm1);
            l0 += p0 + p1; l1 += p2 + p3;
            s[nf][0] = p0; s[nf][1] = p1; s[nf][2] = p2; s[nf][3] = p3;
        }
        m0 = nm0; m1 = nm1;

        // ---- O += P V (split P in-register) ----
#pragma unroll
        for (int kk = 0; kk < 4; kk++) {
            uint32_t ah[4], al[4];
#pragma unroll
            for (int half = 0; half < 2; half++) {
                const float* sp = s[2 * kk + half];
                __nv_bfloat16 h0, h1, h2, h3, lo0, lo1, lo2, lo3;
                split2(sp[0], h0, lo0); split2(sp[1], h1, lo1);
                split2(sp[2], h2, lo2); split2(sp[3], h3, lo3);
                ah[half * 2 + 0] = packbf(h0, h1);  al[half * 2 + 0] = packbf(lo0, lo1);
                ah[half * 2 + 1] = packbf(h2, h3);  al[half * 2 + 1] = packbf(lo2, lo3);
            }
            const uint32_t krow = (uint32_t)((kk * 16 + pv_key) * AT_ROWB);
#pragma unroll
            for (int nf = 0; nf < 8; nf++) {
                uint32_t bh[2], blr[2];
                uint32_t off = krow + (uint32_t)(nf * 8 * 2);
                ldm_x2t(bh,  buf + 2 * AT_KV + off);
                ldm_x2t(blr, buf + 3 * AT_KV + off);
                mma16816(o[nf], ah, bh);
                mma16816(o[nf], ah, blr);
                mma16816(o[nf], al, bh);
            }
        }
        __syncthreads();
    }

    // final l reduction across the 4 lanes sharing each row
    l0 += __shfl_xor_sync(0xffffffffu, l0, 1);
    l0 += __shfl_xor_sync(0xffffffffu, l0, 2);
    l1 += __shfl_xor_sync(0xffffffffu, l1, 1);
    l1 += __shfl_xor_sync(0xffffffffu, l1, 2);
    const float i0 = 1.0f / l0, i1 = 1.0f / l1;

    const size_t t0 = (size_t)b * NS + r0;
#pragma unroll
    for (int nf = 0; nf < 8; nf++) {
        const int c = h * HD + nf * 8 + q4 * 2;
        {
            __nv_bfloat16 h0, h1, lo0, lo1;
            split2(o[nf][0] * i0, h0, lo0);
            split2(o[nf][1] * i0, h1, lo1);
            *(uint32_t*)(ohi + t0 * NDIM + c) = packbf(h0, h1);
            *(uint32_t*)(olo + t0 * NDIM + c) = packbf(lo0, lo1);
        }
        {
            __nv_bfloat16 h0, h1, lo0, lo1;
            split2(o[nf][2] * i1, h0, lo0);
            split2(o[nf][3] * i1, h1, lo1);
            *(uint32_t*)(ohi + (t0 + 8) * NDIM + c) = packbf(h0, h1);
            *(uint32_t*)(olo + (t0 + 8) * NDIM + c) = packbf(lo0, lo1);
        }
    }
}

// ---------------- launch ------------------------------------------------------
extern "C" void kernel_launch(void* const* d_in, const int* in_sizes, int n_in,
                              void* d_out, int out_size) {
    const float* x      = (const float*)d_in[0];
    const int*   mask   = (const int*)  d_in[1];
    const float* w_qkv  = (const float*)d_in[2];
    const float* b_qkv  = (const float*)d_in[3];
    const float* w_proj = (const float*)d_in[4];
    const float* b_proj = (const float*)d_in[5];
    const float* g1     = (const float*)d_in[6];
    const float* be1    = (const float*)d_in[7];
    const float* g2     = (const float*)d_in[8];
    const float* be2    = (const float*)d_in[9];
    const float* w1     = (const float*)d_in[10];
    const float* b1     = (const float*)d_in[11];
    const float* w2     = (const float*)d_in[12];
    const float* b2     = (const float*)d_in[13];
    float* out = (float*)d_out;

    float *x2_p;
    __nv_bfloat16 *ahi, *alo, *bhi, *blo;
    __nv_bfloat16 *qh, *ql, *kh, *kl, *vh, *vl;
    uint32_t* mb;
    __nv_bfloat16 *wqh, *wql, *wph, *wpl, *w1h, *w1l, *w2h, *w2l;
    cudaGetSymbolAddress((void**)&x2_p,  g_x2);
    cudaGetSymbolAddress((void**)&ahi,   g_ahi);
    cudaGetSymbolAddress((void**)&alo,   g_alo);
    cudaGetSymbolAddress((void**)&bhi,   g_bhi);
    cudaGetSymbolAddress((void**)&blo,   g_blo);
    cudaGetSymbolAddress((void**)&qh,    g_qhi);
    cudaGetSymbolAddress((void**)&ql,    g_qlo);
    cudaGetSymbolAddress((void**)&kh,    g_khi);
    cudaGetSymbolAddress((void**)&kl,    g_klo);
    cudaGetSymbolAddress((void**)&vh,    g_vhi);
    cudaGetSymbolAddress((void**)&vl,    g_vlo);
    cudaGetSymbolAddress((void**)&mb,    g_mbits);
    cudaGetSymbolAddress((void**)&wqh,   g_wqkv_hi);
    cudaGetSymbolAddress((void**)&wql,   g_wqkv_lo);
    cudaGetSymbolAddress((void**)&wph,   g_wproj_hi);
    cudaGetSymbolAddress((void**)&wpl,   g_wproj_lo);
    cudaGetSymbolAddress((void**)&w1h,   g_w1_hi);
    cudaGetSymbolAddress((void**)&w1l,   g_w1_lo);
    cudaGetSymbolAddress((void**)&w2h,   g_w2_hi);
    cudaGetSymbolAddress((void**)&w2l,   g_w2_lo);

    cudaFuncSetAttribute(hmma_gemm<0>, cudaFuncAttributeMaxDynamicSharedMemorySize, GEMM_SMEM);
    cudaFuncSetAttribute(hmma_gemm<1>, cudaFuncAttributeMaxDynamicSharedMemorySize, GEMM_SMEM);
    cudaFuncSetAttribute(hmma_gemm<2>, cudaFuncAttributeMaxDynamicSharedMemorySize, GEMM_SMEM);
    cudaFuncSetAttribute(hmma_gemm<3>, cudaFuncAttributeMaxDynamicSharedMemorySize, GEMM_SMEM);
    cudaFuncSetAttribute(attn_hmma,    cudaFuncAttributeMaxDynamicSharedMemorySize, ATTN_SMEM);

    // weight splits + mask pack
    {
        int n4;
        n4 = NDIM * QKVLD / 4; split_kernel<<<(n4 + 255) / 256, 256>>>(w_qkv,  wqh, wql, n4);
        n4 = NDIM * NDIM / 4;  split_kernel<<<(n4 + 255) / 256, 256>>>(w_proj, wph, wpl, n4);
        n4 = NDIM * NHID / 4;  split_kernel<<<(n4 + 255) / 256, 256>>>(w1,     w1h, w1l, n4);
        n4 = NHID * NDIM / 4;  split_kernel<<<(n4 + 255) / 256, 256>>>(w2,     w2h, w2l, n4);
        pack_mask_kernel<<<(NB * NS * 64) / 256, 256>>>(mask, mb);
    }

    // 1) LN1 -> split planes
    ln_split_kernel<<<NM, 256>>>(x, g1, be1, ahi, alo);
    // 2) qkv GEMM -> head-major split planes
    hmma_gemm<3><<<dim3(QKVLD / 128, NM / 128), 256, GEMM_SMEM>>>(
        ahi, alo, wqh, wql, b_qkv, nullptr, nullptr, qh, ql, kh, kl, vh, vl, QKVLD, NDIM);
    // 3) attention -> split planes
    attn_hmma<<<dim3(NS / 128, NH, NB), 256, ATTN_SMEM>>>(
        qh, ql, kh, kl, vh, vl, mb, ahi, alo);
    // 4) x2 = x + attn @ w_proj + b_proj
    hmma_gemm<1><<<dim3(NDIM / 128, NM / 128), 256, GEMM_SMEM>>>(
        ahi, alo, wph, wpl, b_proj, x, x2_p, nullptr, nullptr,
        nullptr, nullptr, nullptr, nullptr, NDIM, NDIM);
    // 5) LN2 -> split planes
    ln_split_kernel<<<NM, 256>>>(x2_p, g2, be2, ahi, alo);
    // 6) hid = gelu(h @ w1 + b1) -> split planes
    hmma_gemm<2><<<dim3(NHID / 128, NM / 128), 256, GEMM_SMEM>>>(
        ahi, alo, w1h, w1l, b1, nullptr, nullptr, bhi, blo,
        nullptr, nullptr, nullptr, nullptr, NHID, NDIM);
    // 7) out = x2 + hid @ w2 + b2
    hmma_gemm<1><<<dim3(NDIM / 128, NM / 128), 256, GEMM_SMEM>>>(
        bhi, blo, w2h, w2l, b2, x2_p, out, nullptr, nullptr,
        nullptr, nullptr, nullptr, nullptr, NDIM, NHID);
}